// round 9
// baseline (speedup 1.0000x reference)
#include <cuda_runtime.h>
#include <cuda_fp16.h>

// VecInt: 7-step scaling-and-squaring integration of [2,128,128,128,3] f32.
//   v0 = vel/128;  v <- v + trilinear_warp(v, v)  x7
//
// R9 = R8 scaled: 4 voxels per thread, contiguous in d (d0..d0+3).
//  - ~36 gather loads in flight per thread (software-pipelined: issue the
//    next voxel's burst before blending the previous one)
//  - contiguous-d voxels overlap gather planes -> L1 line reuse (mechanism
//    measured in R8: L1-work dropped below the single-voxel floor)
// fp16x4 storage, single-copy ping-pong (67MB live set, L2-resident).
// Arithmetic identical to R7/R8 (rel_err 4.6838e-4).

static constexpr int DIMS = 128;
static constexpr int NB   = 2;
static constexpr int NVOX = NB * DIMS * DIMS * DIMS;

// +2 pad: zero-weighted stray read at iw0==127 lands here (zero-init'd).
__device__ __align__(16) uint2 g_bufA[NVOX + 2];
__device__ __align__(16) uint2 g_bufB[NVOX + 2];

__device__ __forceinline__ void h4_to_f3(uint2 u, float& x, float& y, float& z)
{
    __half2 h01 = *reinterpret_cast<__half2*>(&u.x);
    __half2 h23 = *reinterpret_cast<__half2*>(&u.y);
    float2  f01 = __half22float2(h01);
    x = f01.x; y = f01.y; z = __low2float(h23);
}

__device__ __forceinline__ uint2 f3_to_h4(float x, float y, float z)
{
    __half2 h01 = __floats2half2_rn(x, y);
    __half2 h23 = __floats2half2_rn(z, 0.0f);
    uint2 u;
    u.x = *reinterpret_cast<unsigned int*>(&h01);
    u.y = *reinterpret_cast<unsigned int*>(&h23);
    return u;
}

// ---------- pass 0: packed f32x3 -> fp16x4, folding 1/128 -------------------
__global__ __launch_bounds__(256)
void vecint_convert(const float4* __restrict__ in, uint4* __restrict__ out)
{
    const int t = blockIdx.x * blockDim.x + threadIdx.x;
    const float s = 1.0f / 128.0f;
    const float4 a = in[3 * t + 0];
    const float4 b = in[3 * t + 1];
    const float4 c = in[3 * t + 2];
    const uint2 v0 = f3_to_h4(a.x * s, a.y * s, a.z * s);
    const uint2 v1 = f3_to_h4(a.w * s, b.x * s, b.y * s);
    const uint2 v2 = f3_to_h4(b.z * s, b.w * s, c.x * s);
    const uint2 v3 = f3_to_h4(c.y * s, c.z * s, c.w * s);
    out[2 * t + 0] = make_uint4(v0.x, v0.y, v1.x, v1.y);
    out[2 * t + 1] = make_uint4(v2.x, v2.y, v3.x, v3.y);
}

// ---------- per-voxel machinery ---------------------------------------------
struct Vx {
    int   r00, r01, r10, r11, base;
    float f0, f1, f2, w00, w01, w10, w11, ww0, ww1;
};

__device__ __forceinline__ Vx vx_setup(const uint2* __restrict__ in_v,
                                       int b, int d, int h, int w)
{
    Vx v;
    v.base = ((b * DIMS + d) * DIMS + h) * DIMS + w;
    h4_to_f3(in_v[v.base], v.f0, v.f1, v.f2);

    const float ldc = fminf(fmaxf((float)d + v.f0, 0.0f), 127.0f);
    const float lhc = fminf(fmaxf((float)h + v.f1, 0.0f), 127.0f);
    const float lwc = fminf(fmaxf((float)w + v.f2, 0.0f), 127.0f);

    const float fd = floorf(ldc), fh = floorf(lhc), fw = floorf(lwc);
    const int   id0 = (int)fd,  ih0 = (int)fh,  iw0 = (int)fw;
    const float wd1 = ldc - fd, wh1 = lhc - fh;
    const float wd0 = 1.0f - wd1, wh0 = 1.0f - wh1;
    v.ww1 = lwc - fw; v.ww0 = 1.0f - v.ww1;

    const int dd = (id0 < 127) ? (DIMS * DIMS) : 0;
    const int dh = (ih0 < 127) ? DIMS : 0;
    v.r00 = ((b * DIMS + id0) * DIMS + ih0) * DIMS + iw0;
    v.r01 = v.r00 + dh;
    v.r10 = v.r00 + dd;
    v.r11 = v.r10 + dh;

    v.w00 = wd0 * wh0; v.w01 = wd0 * wh1;
    v.w10 = wd1 * wh0; v.w11 = wd1 * wh1;
    return v;
}

struct Gather { uint2 a0, b0, a1, b1, a2, b2, a3, b3; };

__device__ __forceinline__ Gather vx_load(const uint2* __restrict__ in_v,
                                          const Vx& v)
{
    Gather g;
    g.a0 = in_v[v.r00]; g.b0 = in_v[v.r00 + 1];
    g.a1 = in_v[v.r01]; g.b1 = in_v[v.r01 + 1];
    g.a2 = in_v[v.r10]; g.b2 = in_v[v.r10 + 1];
    g.a3 = in_v[v.r11]; g.b3 = in_v[v.r11 + 1];
    return g;
}

__device__ __forceinline__ void vx_blend(const Vx& v, const Gather& g,
                                         float& o0, float& o1, float& o2)
{
    float r0 = 0.0f, r1 = 0.0f, r2 = 0.0f;
    float x0, y0, z0, x1, y1, z1;
#define BLEND(A, B, WDH)                                                  \
    h4_to_f3(A, x0, y0, z0); h4_to_f3(B, x1, y1, z1);                     \
    {   const float g0 = (WDH) * v.ww0, g1 = (WDH) * v.ww1;               \
        r0 = fmaf(g0, x0, fmaf(g1, x1, r0));                              \
        r1 = fmaf(g0, y0, fmaf(g1, y1, r1));                              \
        r2 = fmaf(g0, z0, fmaf(g1, z1, r2)); }
    BLEND(g.a0, g.b0, v.w00)
    BLEND(g.a1, g.b1, v.w01)
    BLEND(g.a2, g.b2, v.w10)
    BLEND(g.a3, g.b3, v.w11)
#undef BLEND
    o0 = v.f0 + r0; o1 = v.f1 + r1; o2 = v.f2 + r2;
}

// ---------- integration step: 4 contiguous-d voxels per thread --------------
template<bool OUT_PACKED>
__global__ __launch_bounds__(256)
void vecint_step(const uint2* __restrict__ in_v,
                 float*       __restrict__ out_p,
                 uint2*       __restrict__ out_v)
{
    const int w  = blockIdx.x * 32 + threadIdx.x;
    const int h  = blockIdx.y * 8  + threadIdx.y;
    const int zb = blockIdx.z;                  // 64: 32 d-quads x 2 batches
    const int b  = zb >> 5;
    const int d0 = (zb & 31) << 2;              // this thread: d0 .. d0+3

    // Setup (4 own-voxel loads overlap), then software-pipelined bursts:
    // issue burst k+1 before blending k, keeping ~2 bursts + blends in flight.
    Vx v0 = vx_setup(in_v, b, d0 + 0, h, w);
    Vx v1 = vx_setup(in_v, b, d0 + 1, h, w);
    Vx v2 = vx_setup(in_v, b, d0 + 2, h, w);
    Vx v3 = vx_setup(in_v, b, d0 + 3, h, w);

    Gather g0 = vx_load(in_v, v0);
    Gather g1 = vx_load(in_v, v1);

    float o00, o01, o02, o10, o11, o12, o20, o21, o22, o30, o31, o32;

    Gather g2 = vx_load(in_v, v2);
    vx_blend(v0, g0, o00, o01, o02);
    Gather g3 = vx_load(in_v, v3);
    vx_blend(v1, g1, o10, o11, o12);
    vx_blend(v2, g2, o20, o21, o22);
    vx_blend(v3, g3, o30, o31, o32);

    if (OUT_PACKED) {
        float* p0 = out_p + (size_t)v0.base * 3;
        p0[0] = o00; p0[1] = o01; p0[2] = o02;
        float* p1 = out_p + (size_t)v1.base * 3;
        p1[0] = o10; p1[1] = o11; p1[2] = o12;
        float* p2 = out_p + (size_t)v2.base * 3;
        p2[0] = o20; p2[1] = o21; p2[2] = o22;
        float* p3 = out_p + (size_t)v3.base * 3;
        p3[0] = o30; p3[1] = o31; p3[2] = o32;
    } else {
        out_v[v0.base] = f3_to_h4(o00, o01, o02);
        out_v[v1.base] = f3_to_h4(o10, o11, o12);
        out_v[v2.base] = f3_to_h4(o20, o21, o22);
        out_v[v3.base] = f3_to_h4(o30, o31, o32);
    }
}

extern "C" void kernel_launch(void* const* d_in, const int* in_sizes, int n_in,
                              void* d_out, int out_size)
{
    (void)in_sizes; (void)n_in; (void)out_size;
    const float4* vel = (const float4*)d_in[0];
    float*        out = (float*)d_out;

    uint2 *A = nullptr, *B = nullptr;
    cudaGetSymbolAddress((void**)&A, g_bufA);
    cudaGetSymbolAddress((void**)&B, g_bufB);

    vecint_convert<<<NVOX / 4 / 256, 256>>>(vel, (uint4*)A);

    const dim3 blk(32, 8, 1);                           // 256 threads
    const dim3 grd(DIMS / 32, DIMS / 8, (DIMS / 4) * NB);  // 4 voxels/thread

    vecint_step<false><<<grd, blk>>>(A, nullptr, B);   // 1
    vecint_step<false><<<grd, blk>>>(B, nullptr, A);   // 2
    vecint_step<false><<<grd, blk>>>(A, nullptr, B);   // 3
    vecint_step<false><<<grd, blk>>>(B, nullptr, A);   // 4
    vecint_step<false><<<grd, blk>>>(A, nullptr, B);   // 5
    vecint_step<false><<<grd, blk>>>(B, nullptr, A);   // 6
    vecint_step<true ><<<grd, blk>>>(A, out, nullptr); // 7
}

// round 10
// speedup vs baseline: 1.0554x; 1.0554x over previous
#include <cuda_runtime.h>
#include <cuda_fp16.h>

// VecInt: 7-step scaling-and-squaring integration of [2,128,128,128,3] f32.
//   v0 = vel/128;  v <- v + trilinear_warp(v, v)  x7
//
// R10 = R8 (the verified optimum: fp16x4 voxels, single-copy ping-pong,
// 2 voxels/thread, front-loaded 2x9 LDG.64 burst, 32 regs / 83% occ) with
// ONE change: the thread's voxel pair is (d, d+1) instead of (d, d+2).
// Adjacent-d voxels overlap 2 of their 3 gather d-planes (vs 1 for d,d+2),
// so more corner loads hit L1 lines already fetched by the sibling voxel.
// Arithmetic identical to R7/R8 (rel_err 4.6838e-4).

static constexpr int DIMS = 128;
static constexpr int NB   = 2;
static constexpr int NVOX = NB * DIMS * DIMS * DIMS;

// +2 pad: zero-weighted stray read at iw0==127 lands here (zero-init'd).
__device__ __align__(16) uint2 g_bufA[NVOX + 2];
__device__ __align__(16) uint2 g_bufB[NVOX + 2];

__device__ __forceinline__ void h4_to_f3(uint2 u, float& x, float& y, float& z)
{
    __half2 h01 = *reinterpret_cast<__half2*>(&u.x);
    __half2 h23 = *reinterpret_cast<__half2*>(&u.y);
    float2  f01 = __half22float2(h01);
    x = f01.x; y = f01.y; z = __low2float(h23);
}

__device__ __forceinline__ uint2 f3_to_h4(float x, float y, float z)
{
    __half2 h01 = __floats2half2_rn(x, y);
    __half2 h23 = __floats2half2_rn(z, 0.0f);
    uint2 u;
    u.x = *reinterpret_cast<unsigned int*>(&h01);
    u.y = *reinterpret_cast<unsigned int*>(&h23);
    return u;
}

// ---------- pass 0: packed f32x3 -> fp16x4, folding 1/128 -------------------
__global__ __launch_bounds__(256)
void vecint_convert(const float4* __restrict__ in, uint4* __restrict__ out)
{
    const int t = blockIdx.x * blockDim.x + threadIdx.x;
    const float s = 1.0f / 128.0f;
    const float4 a = in[3 * t + 0];
    const float4 b = in[3 * t + 1];
    const float4 c = in[3 * t + 2];
    const uint2 v0 = f3_to_h4(a.x * s, a.y * s, a.z * s);
    const uint2 v1 = f3_to_h4(a.w * s, b.x * s, b.y * s);
    const uint2 v2 = f3_to_h4(b.z * s, b.w * s, c.x * s);
    const uint2 v3 = f3_to_h4(c.y * s, c.z * s, c.w * s);
    out[2 * t + 0] = make_uint4(v0.x, v0.y, v1.x, v1.y);
    out[2 * t + 1] = make_uint4(v2.x, v2.y, v3.x, v3.y);
}

// ---------- per-voxel machinery ---------------------------------------------
struct Vx {
    int   r00, r01, r10, r11, base;
    float f0, f1, f2, w00, w01, w10, w11, ww0, ww1;
};

__device__ __forceinline__ Vx vx_setup(const uint2* __restrict__ in_v,
                                       int b, int d, int h, int w)
{
    Vx v;
    v.base = ((b * DIMS + d) * DIMS + h) * DIMS + w;
    h4_to_f3(in_v[v.base], v.f0, v.f1, v.f2);

    const float ldc = fminf(fmaxf((float)d + v.f0, 0.0f), 127.0f);
    const float lhc = fminf(fmaxf((float)h + v.f1, 0.0f), 127.0f);
    const float lwc = fminf(fmaxf((float)w + v.f2, 0.0f), 127.0f);

    const float fd = floorf(ldc), fh = floorf(lhc), fw = floorf(lwc);
    const int   id0 = (int)fd,  ih0 = (int)fh,  iw0 = (int)fw;
    const float wd1 = ldc - fd, wh1 = lhc - fh;
    const float wd0 = 1.0f - wd1, wh0 = 1.0f - wh1;
    v.ww1 = lwc - fw; v.ww0 = 1.0f - v.ww1;

    const int dd = (id0 < 127) ? (DIMS * DIMS) : 0;
    const int dh = (ih0 < 127) ? DIMS : 0;
    v.r00 = ((b * DIMS + id0) * DIMS + ih0) * DIMS + iw0;
    v.r01 = v.r00 + dh;
    v.r10 = v.r00 + dd;
    v.r11 = v.r10 + dh;

    v.w00 = wd0 * wh0; v.w01 = wd0 * wh1;
    v.w10 = wd1 * wh0; v.w11 = wd1 * wh1;
    return v;
}

struct Gather { uint2 a0, b0, a1, b1, a2, b2, a3, b3; };

__device__ __forceinline__ Gather vx_load(const uint2* __restrict__ in_v,
                                          const Vx& v)
{
    Gather g;
    g.a0 = in_v[v.r00]; g.b0 = in_v[v.r00 + 1];
    g.a1 = in_v[v.r01]; g.b1 = in_v[v.r01 + 1];
    g.a2 = in_v[v.r10]; g.b2 = in_v[v.r10 + 1];
    g.a3 = in_v[v.r11]; g.b3 = in_v[v.r11 + 1];
    return g;
}

__device__ __forceinline__ void vx_blend(const Vx& v, const Gather& g,
                                         float& o0, float& o1, float& o2)
{
    float r0 = 0.0f, r1 = 0.0f, r2 = 0.0f;
    float x0, y0, z0, x1, y1, z1;
#define BLEND(A, B, WDH)                                                  \
    h4_to_f3(A, x0, y0, z0); h4_to_f3(B, x1, y1, z1);                     \
    {   const float g0 = (WDH) * v.ww0, g1 = (WDH) * v.ww1;               \
        r0 = fmaf(g0, x0, fmaf(g1, x1, r0));                              \
        r1 = fmaf(g0, y0, fmaf(g1, y1, r1));                              \
        r2 = fmaf(g0, z0, fmaf(g1, z1, r2)); }
    BLEND(g.a0, g.b0, v.w00)
    BLEND(g.a1, g.b1, v.w01)
    BLEND(g.a2, g.b2, v.w10)
    BLEND(g.a3, g.b3, v.w11)
#undef BLEND
    o0 = v.f0 + r0; o1 = v.f1 + r1; o2 = v.f2 + r2;
}

// ---------- integration step: adjacent-d voxel pair per thread --------------
template<bool OUT_PACKED>
__global__ __launch_bounds__(256)
void vecint_step(const uint2* __restrict__ in_v,
                 float*       __restrict__ out_p,
                 uint2*       __restrict__ out_v)
{
    const int w  = blockIdx.x * 32 + threadIdx.x;
    const int h  = blockIdx.y * 4  + threadIdx.y;
    const int zb = blockIdx.z;                  // 64: 32 d-quads x 2 batches
    const int b  = zb >> 5;
    const int d  = ((zb & 31) << 2) + (threadIdx.z << 1);  // pair: d, d+1

    const Vx vA = vx_setup(in_v, b, d,     h, w);
    const Vx vB = vx_setup(in_v, b, d + 1, h, w);
    const Gather gA = vx_load(in_v, vA);
    const Gather gB = vx_load(in_v, vB);

    float a0, a1, a2, b0, b1, b2;
    vx_blend(vA, gA, a0, a1, a2);
    vx_blend(vB, gB, b0, b1, b2);

    if (OUT_PACKED) {
        float* pA = out_p + (size_t)vA.base * 3;
        pA[0] = a0; pA[1] = a1; pA[2] = a2;
        float* pB = out_p + (size_t)vB.base * 3;
        pB[0] = b0; pB[1] = b1; pB[2] = b2;
    } else {
        out_v[vA.base] = f3_to_h4(a0, a1, a2);
        out_v[vB.base] = f3_to_h4(b0, b1, b2);
    }
}

extern "C" void kernel_launch(void* const* d_in, const int* in_sizes, int n_in,
                              void* d_out, int out_size)
{
    (void)in_sizes; (void)n_in; (void)out_size;
    const float4* vel = (const float4*)d_in[0];
    float*        out = (float*)d_out;

    uint2 *A = nullptr, *B = nullptr;
    cudaGetSymbolAddress((void**)&A, g_bufA);
    cudaGetSymbolAddress((void**)&B, g_bufB);

    vecint_convert<<<NVOX / 4 / 256, 256>>>(vel, (uint4*)A);

    const dim3 blk(32, 4, 2);
    const dim3 grd(DIMS / 32, DIMS / 4, (DIMS / 4) * NB);   // 2 voxels/thread

    vecint_step<false><<<grd, blk>>>(A, nullptr, B);   // 1
    vecint_step<false><<<grd, blk>>>(B, nullptr, A);   // 2
    vecint_step<false><<<grd, blk>>>(A, nullptr, B);   // 3
    vecint_step<false><<<grd, blk>>>(B, nullptr, A);   // 4
    vecint_step<false><<<grd, blk>>>(A, nullptr, B);   // 5
    vecint_step<false><<<grd, blk>>>(B, nullptr, A);   // 6
    vecint_step<true ><<<grd, blk>>>(A, out, nullptr); // 7
}

// round 11
// speedup vs baseline: 1.0713x; 1.0151x over previous
#include <cuda_runtime.h>
#include <cuda_fp16.h>

// VecInt: 7-step scaling-and-squaring integration of [2,128,128,128,3] f32.
//   v0 = vel/128;  v <- v + trilinear_warp(v, v)  x7
//
// R11 = R10 (fp16x4 voxels, single-copy ping-pong, adjacent-d voxel pair per
// thread, front-loaded 2x9 LDG.64 gather burst; 32 regs, 83% occ) plus:
//  - __stcs on the final packed-f32 output (never re-read; stop it evicting
//    the gather volume from L2 during pass 7)
//  - __ldcs on the convert input (read-once 100MB; keep L2 for the A-buffer
//    that pass 1 immediately re-reads)
//  - explicitly interleaved A/B gather bursts + shared pair addressing
// Arithmetic identical to R7-R10 (rel_err 4.6838e-4).

static constexpr int DIMS = 128;
static constexpr int NB   = 2;
static constexpr int NVOX = NB * DIMS * DIMS * DIMS;
static constexpr int DSTRIDE = DIMS * DIMS;           // 16384

// +2 pad: zero-weighted stray read at iw0==127 lands here (zero-init'd).
__device__ __align__(16) uint2 g_bufA[NVOX + 2];
__device__ __align__(16) uint2 g_bufB[NVOX + 2];

__device__ __forceinline__ void h4_to_f3(uint2 u, float& x, float& y, float& z)
{
    __half2 h01 = *reinterpret_cast<__half2*>(&u.x);
    __half2 h23 = *reinterpret_cast<__half2*>(&u.y);
    float2  f01 = __half22float2(h01);
    x = f01.x; y = f01.y; z = __low2float(h23);
}

__device__ __forceinline__ uint2 f3_to_h4(float x, float y, float z)
{
    __half2 h01 = __floats2half2_rn(x, y);
    __half2 h23 = __floats2half2_rn(z, 0.0f);
    uint2 u;
    u.x = *reinterpret_cast<unsigned int*>(&h01);
    u.y = *reinterpret_cast<unsigned int*>(&h23);
    return u;
}

// ---------- pass 0: packed f32x3 -> fp16x4, folding 1/128 -------------------
__global__ __launch_bounds__(256)
void vecint_convert(const float4* __restrict__ in, uint4* __restrict__ out)
{
    const int t = blockIdx.x * blockDim.x + threadIdx.x;
    const float s = 1.0f / 128.0f;
    const float4 a = __ldcs(in + 3 * t + 0);   // read-once: evict-first
    const float4 b = __ldcs(in + 3 * t + 1);
    const float4 c = __ldcs(in + 3 * t + 2);
    const uint2 v0 = f3_to_h4(a.x * s, a.y * s, a.z * s);
    const uint2 v1 = f3_to_h4(a.w * s, b.x * s, b.y * s);
    const uint2 v2 = f3_to_h4(b.z * s, b.w * s, c.x * s);
    const uint2 v3 = f3_to_h4(c.y * s, c.z * s, c.w * s);
    out[2 * t + 0] = make_uint4(v0.x, v0.y, v1.x, v1.y);
    out[2 * t + 1] = make_uint4(v2.x, v2.y, v3.x, v3.y);
}

// ---------- per-voxel machinery ---------------------------------------------
struct Vx {
    int   r00, r01, r10, r11;
    float f0, f1, f2, w00, w01, w10, w11, ww0, ww1;
};

__device__ __forceinline__ Vx vx_setup(uint2 own, int b, float df, float hf,
                                       float wf, int h_i, int w_i)
{
    Vx v;
    h4_to_f3(own, v.f0, v.f1, v.f2);

    const float ldc = fminf(fmaxf(df + v.f0, 0.0f), 127.0f);
    const float lhc = fminf(fmaxf(hf + v.f1, 0.0f), 127.0f);
    const float lwc = fminf(fmaxf(wf + v.f2, 0.0f), 127.0f);

    const float fd = floorf(ldc), fh = floorf(lhc), fw = floorf(lwc);
    const int   id0 = (int)fd,  ih0 = (int)fh,  iw0 = (int)fw;
    const float wd1 = ldc - fd, wh1 = lhc - fh;
    const float wd0 = 1.0f - wd1, wh0 = 1.0f - wh1;
    v.ww1 = lwc - fw; v.ww0 = 1.0f - v.ww1;

    const int dd = (id0 < 127) ? DSTRIDE : 0;
    const int dh = (ih0 < 127) ? DIMS : 0;
    v.r00 = ((b * DIMS + id0) * DIMS + ih0) * DIMS + iw0;
    v.r01 = v.r00 + dh;
    v.r10 = v.r00 + dd;
    v.r11 = v.r10 + dh;

    v.w00 = wd0 * wh0; v.w01 = wd0 * wh1;
    v.w10 = wd1 * wh0; v.w11 = wd1 * wh1;
    (void)h_i; (void)w_i;
    return v;
}

struct Gather { uint2 a0, b0, a1, b1, a2, b2, a3, b3; };

__device__ __forceinline__ void vx_blend(const Vx& v, const Gather& g,
                                         float& o0, float& o1, float& o2)
{
    float r0 = 0.0f, r1 = 0.0f, r2 = 0.0f;
    float x0, y0, z0, x1, y1, z1;
#define BLEND(A, B, WDH)                                                  \
    h4_to_f3(A, x0, y0, z0); h4_to_f3(B, x1, y1, z1);                     \
    {   const float g0 = (WDH) * v.ww0, g1 = (WDH) * v.ww1;               \
        r0 = fmaf(g0, x0, fmaf(g1, x1, r0));                              \
        r1 = fmaf(g0, y0, fmaf(g1, y1, r1));                              \
        r2 = fmaf(g0, z0, fmaf(g1, z1, r2)); }
    BLEND(g.a0, g.b0, v.w00)
    BLEND(g.a1, g.b1, v.w01)
    BLEND(g.a2, g.b2, v.w10)
    BLEND(g.a3, g.b3, v.w11)
#undef BLEND
    o0 = v.f0 + r0; o1 = v.f1 + r1; o2 = v.f2 + r2;
}

// ---------- integration step: adjacent-d voxel pair per thread --------------
template<bool OUT_PACKED>
__global__ __launch_bounds__(256)
void vecint_step(const uint2* __restrict__ in_v,
                 float*       __restrict__ out_p,
                 uint2*       __restrict__ out_v)
{
    const int w  = blockIdx.x * 32 + threadIdx.x;
    const int h  = blockIdx.y * 4  + threadIdx.y;
    const int zb = blockIdx.z;                  // 64: 32 d-quads x 2 batches
    const int b  = zb >> 5;
    const int d  = ((zb & 31) << 2) + (threadIdx.z << 1);  // pair: d, d+1

    const int baseA = ((b * DIMS + d) * DIMS + h) * DIMS + w;
    const int baseB = baseA + DSTRIDE;

    // Own-voxel loads first (both in flight).
    const uint2 ownA = in_v[baseA];
    const uint2 ownB = in_v[baseB];

    const float hf = (float)h, wf = (float)w, df = (float)d;

    const Vx vA = vx_setup(ownA, b, df,        hf, wf, h, w);
    const Vx vB = vx_setup(ownB, b, df + 1.0f, hf, wf, h, w);

    // Interleaved front-loaded gather bursts (~16 loads in flight).
    Gather gA, gB;
    gA.a0 = in_v[vA.r00];     gB.a0 = in_v[vB.r00];
    gA.b0 = in_v[vA.r00 + 1]; gB.b0 = in_v[vB.r00 + 1];
    gA.a1 = in_v[vA.r01];     gB.a1 = in_v[vB.r01];
    gA.b1 = in_v[vA.r01 + 1]; gB.b1 = in_v[vB.r01 + 1];
    gA.a2 = in_v[vA.r10];     gB.a2 = in_v[vB.r10];
    gA.b2 = in_v[vA.r10 + 1]; gB.b2 = in_v[vB.r10 + 1];
    gA.a3 = in_v[vA.r11];     gB.a3 = in_v[vB.r11];
    gA.b3 = in_v[vA.r11 + 1]; gB.b3 = in_v[vB.r11 + 1];

    float a0, a1, a2, b0, b1, b2;
    vx_blend(vA, gA, a0, a1, a2);
    vx_blend(vB, gB, b0, b1, b2);

    if (OUT_PACKED) {
        // Output is never re-read: streaming stores keep L2 for the gathers.
        float* pA = out_p + (size_t)baseA * 3;
        __stcs(pA + 0, a0); __stcs(pA + 1, a1); __stcs(pA + 2, a2);
        float* pB = out_p + (size_t)baseB * 3;
        __stcs(pB + 0, b0); __stcs(pB + 1, b1); __stcs(pB + 2, b2);
    } else {
        out_v[baseA] = f3_to_h4(a0, a1, a2);
        out_v[baseB] = f3_to_h4(b0, b1, b2);
    }
}

extern "C" void kernel_launch(void* const* d_in, const int* in_sizes, int n_in,
                              void* d_out, int out_size)
{
    (void)in_sizes; (void)n_in; (void)out_size;
    const float4* vel = (const float4*)d_in[0];
    float*        out = (float*)d_out;

    uint2 *A = nullptr, *B = nullptr;
    cudaGetSymbolAddress((void**)&A, g_bufA);
    cudaGetSymbolAddress((void**)&B, g_bufB);

    vecint_convert<<<NVOX / 4 / 256, 256>>>(vel, (uint4*)A);

    const dim3 blk(32, 4, 2);
    const dim3 grd(DIMS / 32, DIMS / 4, (DIMS / 4) * NB);   // 2 voxels/thread

    vecint_step<false><<<grd, blk>>>(A, nullptr, B);   // 1
    vecint_step<false><<<grd, blk>>>(B, nullptr, A);   // 2
    vecint_step<false><<<grd, blk>>>(A, nullptr, B);   // 3
    vecint_step<false><<<grd, blk>>>(B, nullptr, A);   // 4
    vecint_step<false><<<grd, blk>>>(A, nullptr, B);   // 5
    vecint_step<false><<<grd, blk>>>(B, nullptr, A);   // 6
    vecint_step<true ><<<grd, blk>>>(A, out, nullptr); // 7
}